// round 14
// baseline (speedup 1.0000x reference)
#include <cuda_runtime.h>
#include <cuda_fp16.h>
#include <math.h>
#include <stdint.h>

// Problem constants
#define T_TOKENS 2048
#define HIDDEN   2048
#define INTER    5632
#define NEXP     8
#define TOPK     2
#define NPAIRS   (T_TOKENS * TOPK)   // 4096
#define CAP      2048

// ---------------- device scratch ----------------
__device__ int d_cnt[NEXP];
__device__ int d_list[NEXP * CAP];
__device__ int d_eid[NPAIRS];
__device__ float d_wgt[NPAIRS];

__device__ __align__(16) float d_G[(size_t)NPAIRS * INTER];   // gate, then act (in-place)
__device__ __align__(16) float d_U[(size_t)NPAIRS * INTER];   // up
__device__ __align__(16) float d_Y[(size_t)NPAIRS * HIDDEN];  // per-pair down output

// ---------------- small kernels ----------------
__global__ void init_kernel() {
    if (threadIdx.x < NEXP) d_cnt[threadIdx.x] = 0;
}

__global__ void router_kernel(const float* __restrict__ x, const float* __restrict__ wr) {
    int warp = threadIdx.x >> 5;
    int lane = threadIdx.x & 31;
    int t = blockIdx.x * 8 + warp;
    if (t >= T_TOKENS) return;

    float acc[NEXP];
#pragma unroll
    for (int e = 0; e < NEXP; e++) acc[e] = 0.f;
    const float* xr = x + (size_t)t * HIDDEN;
    for (int j = lane; j < HIDDEN; j += 32) {
        float xv = xr[j];
#pragma unroll
        for (int e = 0; e < NEXP; e++) acc[e] += xv * wr[e * HIDDEN + j];
    }
#pragma unroll
    for (int e = 0; e < NEXP; e++) {
#pragma unroll
        for (int off = 16; off; off >>= 1)
            acc[e] += __shfl_xor_sync(0xffffffffu, acc[e], off);
    }
    if (lane == 0) {
        int e0 = 0;
#pragma unroll
        for (int e = 1; e < NEXP; e++) if (acc[e] > acc[e0]) e0 = e;
        int e1 = -1;
#pragma unroll
        for (int e = 0; e < NEXP; e++) {
            if (e == e0) continue;
            if (e1 < 0 || acc[e] > acc[e1]) e1 = e;
        }
        float v0 = acc[e0], v1 = acc[e1];
        float w1 = 1.f / (1.f + expf(v0 - v1));
        float w0 = 1.f - w1;
        d_eid[2 * t] = e0;  d_eid[2 * t + 1] = e1;
        d_wgt[2 * t] = w0;  d_wgt[2 * t + 1] = w1;
    }
}

__global__ void compact_kernel() {
    int p = blockIdx.x * blockDim.x + threadIdx.x;
    if (p >= NPAIRS) return;
    int e = d_eid[p];
    int pos = atomicAdd(&d_cnt[e], 1);
    d_list[e * CAP + pos] = p;
}

// ---------------- helpers ----------------
__device__ __forceinline__ uint32_t smem_u32(const void* p) {
    uint32_t a;
    asm("{ .reg .u64 t; cvta.to.shared.u64 t, %1; cvt.u32.u64 %0, t; }" : "=r"(a) : "l"(p));
    return a;
}
// pack two f32 into f16x2: lo half = a, hi half = b
__device__ __forceinline__ uint32_t packf16(float a, float b) {
    uint32_t d;
    asm("cvt.rn.f16x2.f32 %0, %1, %2;" : "=r"(d) : "f"(b), "f"(a));
    return d;
}
__device__ __forceinline__ void mma_f16(float* c, const uint32_t* a, const uint32_t* b) {
    asm volatile("mma.sync.aligned.m16n8k16.row.col.f32.f16.f16.f32 "
                 "{%0,%1,%2,%3}, {%4,%5,%6,%7}, {%8,%9}, {%0,%1,%2,%3};"
                 : "+f"(c[0]), "+f"(c[1]), "+f"(c[2]), "+f"(c[3])
                 : "r"(a[0]), "r"(a[1]), "r"(a[2]), "r"(a[3]),
                   "r"(b[0]), "r"(b[1]));
}
__device__ __forceinline__ void ldm4(uint32_t* d, uint32_t addr) {
    asm volatile("ldmatrix.sync.aligned.m8n8.x4.shared.b16 {%0,%1,%2,%3}, [%4];"
                 : "=r"(d[0]), "=r"(d[1]), "=r"(d[2]), "=r"(d[3]) : "r"(addr));
}

// ---------------- expert-grouped fp16 tensor GEMM (register-convert, 2 CTA/SM) ----------------
// C[pid][n] = sum_k A[pid>>shift][k] * B_e[n][k]
// Tile: BM=128, BN=128, BK=32. 256 threads, 8 warps in 2(m) x 4(n), warp tile 64x32.
// fp32 loaded via LDG into regs, cvt to fp16x2 in regs, STS fp16 only. fp32 never in smem.
#define BK 32
#define RS2B 80                                 // fp16 tile row stride in BYTES (64B data + 16 pad)
#define TILE_B (256 * RS2B)                     // one stage: 256 rows (A 0-127, B 128-255)
#define PIDOFF (2 * TILE_B)
#define DYN_BYTES (PIDOFF + 128 * 4 + 16)

__global__ __launch_bounds__(256, 2)
void gemm_tc(const float* __restrict__ Aext, const float* __restrict__ Ball,
             int N, int K, int lda, int shift, int asel, int csel)
{
    int e = blockIdx.z;
    int n_e = d_cnt[e];
    int mbase = blockIdx.y * 128;
    if (mbase >= n_e) return;
    int nbase = blockIdx.x * 128;

    const float* A = asel ? d_G : Aext;
    float* C = (csel == 0) ? d_G : (csel == 1) ? d_U : d_Y;
    const float* B = Ball + (size_t)e * N * K;

    extern __shared__ float sm[];
    int* s_pid = (int*)((char*)sm + PIDOFF);
    uint32_t smbase = smem_u32(sm);
    char* h16 = (char*)sm;

    int tid = threadIdx.x;
    int lane = tid & 31;
    int wid = tid >> 5;
    int wm = wid & 1;          // 0..1  (64 rows)
    int wn = wid >> 1;         // 0..3  (32 cols)

    if (tid < 128) {
        int lp = mbase + tid;
        s_pid[tid] = d_list[e * CAP + (lp < n_e ? lp : mbase)];
    }
    __syncthreads();

    // loader mapping: 4 chunks/thread per operand; chunk i covers (row = (tid+i*256)>>3, 4 floats at c4)
    // gmem byte offsets (32-bit; regions < 4GB) and smem fp16 byte offsets
    uint32_t aGo[4], bGo[4];
    uint32_t aS[4], bS[4];
#pragma unroll
    for (int i = 0; i < 4; i++) {
        int idx = tid + i * 256;          // 0..1023
        int row = idx >> 3;
        int c4  = (idx & 7) * 4;          // float index 0,4,..,28
        aGo[i] = (uint32_t)(((size_t)(s_pid[row] >> shift) * lda + c4) * 4);
        bGo[i] = (uint32_t)(((size_t)(nbase + row) * K + c4) * 4);
        aS[i]  = (uint32_t)(row * RS2B + c4 * 2);
        bS[i]  = (uint32_t)((128 + row) * RS2B + c4 * 2);
    }

    int KT = K / BK;

    float acc[4][4][4];
#pragma unroll
    for (int mt = 0; mt < 4; mt++)
#pragma unroll
        for (int nt = 0; nt < 4; nt++)
#pragma unroll
            for (int q = 0; q < 4; q++) acc[mt][nt][q] = 0.f;

    // ---- ldmatrix per-lane addresses within a stage (byte offsets) ----
    int lg = lane >> 3, lr = lane & 7;
    uint32_t aoff[4];
#pragma unroll
    for (int mt = 0; mt < 4; mt++) {
        int row = wm * 64 + mt * 16 + ((lg & 1) << 3) + lr;
        aoff[mt] = (uint32_t)(row * RS2B + ((lg >> 1) << 4));
    }
    uint32_t boff[2];
#pragma unroll
    for (int ntp = 0; ntp < 2; ntp++) {
        int row = 128 + wn * 32 + ntp * 16 + ((lg >> 1) << 3) + lr;
        boff[ntp] = (uint32_t)(row * RS2B + ((lg & 1) << 4));
    }

    // ---- prologue: load kb=0 through registers into stage 0 ----
    {
        float4 ra[4], rb[4];
#pragma unroll
        for (int i = 0; i < 4; i++) ra[i] = *(const float4*)((const char*)A + aGo[i]);
#pragma unroll
        for (int i = 0; i < 4; i++) rb[i] = *(const float4*)((const char*)B + bGo[i]);
#pragma unroll
        for (int i = 0; i < 4; i++) {
            uint2 v = make_uint2(packf16(ra[i].x, ra[i].y), packf16(ra[i].z, ra[i].w));
            *(uint2*)(h16 + aS[i]) = v;
        }
#pragma unroll
        for (int i = 0; i < 4; i++) {
            uint2 v = make_uint2(packf16(rb[i].x, rb[i].y), packf16(rb[i].z, rb[i].w));
            *(uint2*)(h16 + bS[i]) = v;
        }
    }
    __syncthreads();

    for (int kb = 0; kb < KT; kb++) {
        int st = kb & 1;
        bool pf = (kb + 1 < KT);
        uint32_t go = (uint32_t)((kb + 1) * 128);   // BK floats = 128 bytes per kb
        uint32_t stb = smbase + (uint32_t)(st * TILE_B);

        float4 ra[4], rb[4];
        if (pf) {
#pragma unroll
            for (int i = 0; i < 4; i++) ra[i] = *(const float4*)((const char*)A + aGo[i] + go);
        }

        // ---- ks = 0 ----
        uint32_t af[4][4], bf[2][4];
#pragma unroll
        for (int mt = 0; mt < 4; mt++) ldm4(af[mt], stb + aoff[mt]);
#pragma unroll
        for (int ntp = 0; ntp < 2; ntp++) ldm4(bf[ntp], stb + boff[ntp]);
#pragma unroll
        for (int mt = 0; mt < 4; mt++)
#pragma unroll
            for (int ntp = 0; ntp < 2; ntp++) {
                mma_f16(acc[mt][2 * ntp],     af[mt], &bf[ntp][0]);
                mma_f16(acc[mt][2 * ntp + 1], af[mt], &bf[ntp][2]);
            }

        // cvt A early (frees ra), issue B loads (latency hides under ks=1)
        uint2 pkA[4];
        if (pf) {
#pragma unroll
            for (int i = 0; i < 4; i++)
                pkA[i] = make_uint2(packf16(ra[i].x, ra[i].y), packf16(ra[i].z, ra[i].w));
#pragma unroll
            for (int i = 0; i < 4; i++) rb[i] = *(const float4*)((const char*)B + bGo[i] + go);
        }

        // ---- ks = 1 ----
#pragma unroll
        for (int mt = 0; mt < 4; mt++) ldm4(af[mt], stb + aoff[mt] + 32);
#pragma unroll
        for (int ntp = 0; ntp < 2; ntp++) ldm4(bf[ntp], stb + boff[ntp] + 32);
#pragma unroll
        for (int mt = 0; mt < 4; mt++)
#pragma unroll
            for (int ntp = 0; ntp < 2; ntp++) {
                mma_f16(acc[mt][2 * ntp],     af[mt], &bf[ntp][0]);
                mma_f16(acc[mt][2 * ntp + 1], af[mt], &bf[ntp][2]);
            }

        __syncthreads();                 // all warps done reading stage (st^1) last iter & stage st now
        if (pf) {
            char* nb = h16 + (st ^ 1) * TILE_B;
#pragma unroll
            for (int i = 0; i < 4; i++) *(uint2*)(nb + aS[i]) = pkA[i];
#pragma unroll
            for (int i = 0; i < 4; i++) {
                uint2 v = make_uint2(packf16(rb[i].x, rb[i].y), packf16(rb[i].z, rb[i].w));
                *(uint2*)(nb + bS[i]) = v;
            }
        }
        __syncthreads();                 // next stage ready
    }

    // ---- epilogue: scatter accum rows via pid list ----
    int gid = lane >> 2;
    int tig = lane & 3;
#pragma unroll
    for (int mt = 0; mt < 4; mt++) {
        int mrow0 = wm * 64 + mt * 16 + gid;
        int mrow1 = mrow0 + 8;
        bool v0 = (mbase + mrow0) < n_e;
        bool v1 = (mbase + mrow1) < n_e;
        float* c0 = v0 ? (C + (size_t)s_pid[mrow0] * N + nbase + wn * 32 + tig * 2) : (float*)0;
        float* c1 = v1 ? (C + (size_t)s_pid[mrow1] * N + nbase + wn * 32 + tig * 2) : (float*)0;
#pragma unroll
        for (int nt = 0; nt < 4; nt++) {
            if (v0) *(float2*)(c0 + nt * 8) = make_float2(acc[mt][nt][0], acc[mt][nt][1]);
            if (v1) *(float2*)(c1 + nt * 8) = make_float2(acc[mt][nt][2], acc[mt][nt][3]);
        }
    }
}

// ---------------- elementwise ----------------
// act = silu(G) * U, written in place into G (fp32; GEMM3 converts at register staging)
__global__ void act_kernel() {
    size_t i = (size_t)blockIdx.x * blockDim.x + threadIdx.x;
    if (i >= (size_t)NPAIRS * INTER / 4) return;
    float4 g = ((const float4*)d_G)[i];
    float4 u = ((const float4*)d_U)[i];
    float4 o;
    o.x = g.x / (1.f + expf(-g.x)) * u.x;
    o.y = g.y / (1.f + expf(-g.y)) * u.y;
    o.z = g.z / (1.f + expf(-g.z)) * u.z;
    o.w = g.w / (1.f + expf(-g.w)) * u.w;
    ((float4*)d_G)[i] = o;
}

__global__ void combine_kernel(float* __restrict__ out) {
    int idx = blockIdx.x * blockDim.x + threadIdx.x;
    if (idx >= T_TOKENS * HIDDEN / 4) return;
    int t = idx / (HIDDEN / 4);
    int h4 = idx % (HIDDEN / 4);
    float w0 = d_wgt[2 * t], w1 = d_wgt[2 * t + 1];
    float4 a = ((const float4*)d_Y)[(size_t)(2 * t) * (HIDDEN / 4) + h4];
    float4 b = ((const float4*)d_Y)[(size_t)(2 * t + 1) * (HIDDEN / 4) + h4];
    float4 o;
    o.x = w0 * a.x + w1 * b.x;
    o.y = w0 * a.y + w1 * b.y;
    o.z = w0 * a.z + w1 * b.z;
    o.w = w0 * a.w + w1 * b.w;
    ((float4*)out)[idx] = o;
}

// ---------------- launch ----------------
extern "C" void kernel_launch(void* const* d_in, const int* in_sizes, int n_in,
                              void* d_out, int out_size) {
    const float* x  = (const float*)d_in[0];
    const float* wr = (const float*)d_in[1];
    const float* wg = (const float*)d_in[2];
    const float* wu = (const float*)d_in[3];
    const float* wd = (const float*)d_in[4];
    float* out = (float*)d_out;

    cudaFuncSetAttribute(gemm_tc, cudaFuncAttributeMaxDynamicSharedMemorySize, DYN_BYTES);

    init_kernel<<<1, 32>>>();
    router_kernel<<<T_TOKENS / 8, 256>>>(x, wr);
    compact_kernel<<<NPAIRS / 256, 256>>>();

    // G = x @ Wg^T   (N=INTER, K=HIDDEN)
    dim3 g1(INTER / 128, CAP / 128, NEXP);
    gemm_tc<<<g1, 256, DYN_BYTES>>>(x, wg, INTER, HIDDEN, HIDDEN, 1, 0, 0);
    // U = x @ Wu^T
    gemm_tc<<<g1, 256, DYN_BYTES>>>(x, wu, INTER, HIDDEN, HIDDEN, 1, 0, 1);

    // act = silu(G) * U
    size_t total4 = (size_t)NPAIRS * INTER / 4;
    act_kernel<<<(unsigned)((total4 + 255) / 256), 256>>>();

    // Y = act @ Wd^T  (N=HIDDEN, K=INTER)
    dim3 g3(HIDDEN / 128, CAP / 128, NEXP);
    gemm_tc<<<g3, 256, DYN_BYTES>>>(nullptr, wd, HIDDEN, INTER, INTER, 0, 1, 2);

    combine_kernel<<<(T_TOKENS * HIDDEN / 4) / 256, 256>>>(out);
}

// round 15
// speedup vs baseline: 1.1999x; 1.1999x over previous
#include <cuda_runtime.h>
#include <cuda_fp16.h>
#include <math.h>
#include <stdint.h>

// Problem constants
#define T_TOKENS 2048
#define HIDDEN   2048
#define INTER    5632
#define NEXP     8
#define TOPK     2
#define NPAIRS   (T_TOKENS * TOPK)   // 4096
#define CAP      2048
#define WSZ      (NEXP * INTER * HIDDEN)   // elements per weight tensor (92.3M)

// ---------------- device scratch ----------------
__device__ int d_cnt[NEXP];
__device__ int d_list[NEXP * CAP];
__device__ int d_eid[NPAIRS];
__device__ float d_wgt[NPAIRS];

__device__ __align__(16) __half d_Wgh[(size_t)WSZ];
__device__ __align__(16) __half d_Wuh[(size_t)WSZ];
__device__ __align__(16) __half d_Wdh[(size_t)WSZ];
__device__ __align__(16) __half d_Xh[(size_t)T_TOKENS * HIDDEN];
__device__ __align__(16) __half d_Ah[(size_t)NPAIRS * INTER];   // fp16 act
__device__ __align__(16) float d_G[(size_t)NPAIRS * INTER];     // gate (fp32)
__device__ __align__(16) float d_U[(size_t)NPAIRS * INTER];     // up (fp32)
__device__ __align__(16) float d_Y[(size_t)NPAIRS * HIDDEN];    // down output (fp32)

// ---------------- small kernels ----------------
__global__ void init_kernel() {
    if (threadIdx.x < NEXP) d_cnt[threadIdx.x] = 0;
}

__global__ void router_kernel(const float* __restrict__ x, const float* __restrict__ wr) {
    int warp = threadIdx.x >> 5;
    int lane = threadIdx.x & 31;
    int t = blockIdx.x * 8 + warp;
    if (t >= T_TOKENS) return;

    float acc[NEXP];
#pragma unroll
    for (int e = 0; e < NEXP; e++) acc[e] = 0.f;
    const float* xr = x + (size_t)t * HIDDEN;
    for (int j = lane; j < HIDDEN; j += 32) {
        float xv = xr[j];
#pragma unroll
        for (int e = 0; e < NEXP; e++) acc[e] += xv * wr[e * HIDDEN + j];
    }
#pragma unroll
    for (int e = 0; e < NEXP; e++) {
#pragma unroll
        for (int off = 16; off; off >>= 1)
            acc[e] += __shfl_xor_sync(0xffffffffu, acc[e], off);
    }
    if (lane == 0) {
        int e0 = 0;
#pragma unroll
        for (int e = 1; e < NEXP; e++) if (acc[e] > acc[e0]) e0 = e;
        int e1 = -1;
#pragma unroll
        for (int e = 0; e < NEXP; e++) {
            if (e == e0) continue;
            if (e1 < 0 || acc[e] > acc[e1]) e1 = e;
        }
        float v0 = acc[e0], v1 = acc[e1];
        float w1 = 1.f / (1.f + expf(v0 - v1));
        float w0 = 1.f - w1;
        d_eid[2 * t] = e0;  d_eid[2 * t + 1] = e1;
        d_wgt[2 * t] = w0;  d_wgt[2 * t + 1] = w1;
    }
}

__global__ void compact_kernel() {
    int p = blockIdx.x * blockDim.x + threadIdx.x;
    if (p >= NPAIRS) return;
    int e = d_eid[p];
    int pos = atomicAdd(&d_cnt[e], 1);
    d_list[e * CAP + pos] = p;
}

// ---------------- helpers ----------------
__device__ __forceinline__ uint32_t smem_u32(const void* p) {
    uint32_t a;
    asm("{ .reg .u64 t; cvta.to.shared.u64 t, %1; cvt.u32.u64 %0, t; }" : "=r"(a) : "l"(p));
    return a;
}
__device__ __forceinline__ uint32_t packf16(float a, float b) {   // lo=a, hi=b
    uint32_t d;
    asm("cvt.rn.f16x2.f32 %0, %1, %2;" : "=r"(d) : "f"(b), "f"(a));
    return d;
}
__device__ __forceinline__ void mma_f16(float* c, const uint32_t* a, const uint32_t* b) {
    asm volatile("mma.sync.aligned.m16n8k16.row.col.f32.f16.f16.f32 "
                 "{%0,%1,%2,%3}, {%4,%5,%6,%7}, {%8,%9}, {%0,%1,%2,%3};"
                 : "+f"(c[0]), "+f"(c[1]), "+f"(c[2]), "+f"(c[3])
                 : "r"(a[0]), "r"(a[1]), "r"(a[2]), "r"(a[3]),
                   "r"(b[0]), "r"(b[1]));
}
__device__ __forceinline__ void ldm4(uint32_t* d, uint32_t addr) {
    asm volatile("ldmatrix.sync.aligned.m8n8.x4.shared.b16 {%0,%1,%2,%3}, [%4];"
                 : "=r"(d[0]), "=r"(d[1]), "=r"(d[2]), "=r"(d[3]) : "r"(addr));
}
__device__ __forceinline__ void cp16(uint32_t smem_dst, const void* gptr) {
    asm volatile("cp.async.cg.shared.global [%0], [%1], 16;" :: "r"(smem_dst), "l"(gptr));
}

// ---------------- fp32 -> fp16 streaming conversion ----------------
// dsel: 0->d_Wgh 1->d_Wuh 2->d_Wdh 3->d_Xh
__global__ __launch_bounds__(256) void cvt_half_kernel(const float* __restrict__ src, int dsel, int n4) {
    int i = blockIdx.x * blockDim.x + threadIdx.x;
    if (i >= n4) return;
    __half* dst = (dsel == 0) ? d_Wgh : (dsel == 1) ? d_Wuh : (dsel == 2) ? d_Wdh : d_Xh;
    float4 v = ((const float4*)src)[i];
    uint2 o = make_uint2(packf16(v.x, v.y), packf16(v.z, v.w));
    ((uint2*)dst)[i] = o;
}

// ---------------- expert-grouped pure-fp16 tensor GEMM ----------------
// C[pid][n] = sum_k A[pid>>shift][k] * B_e[n][k]   (A, B fp16 in gmem; C fp32)
// Tile: BM=128, BN=128, BK=32. 256 threads, 8 warps in 2(m) x 4(n), warp tile 64x32.
// asel: 0 -> d_Xh, 1 -> d_Ah.  bsel: 0 -> d_Wgh, 1 -> d_Wuh, 2 -> d_Wdh.
#define BK 32
#define RS2B 80                                 // fp16 row stride bytes (64B data + 16 pad)
#define TILE_B (256 * RS2B)                     // stage: A rows 0-127, B rows 128-255
#define NSTAGE 3
#define PIDOFF (NSTAGE * TILE_B)
#define DYN_BYTES (PIDOFF + 128 * 4 + 16)

__global__ __launch_bounds__(256, 2)
void gemm_h(int N, int K, int lda, int shift, int asel, int bsel, int csel)
{
    int e = blockIdx.z;
    int n_e = d_cnt[e];
    int mbase = blockIdx.y * 128;
    if (mbase >= n_e) return;
    int nbase = blockIdx.x * 128;

    const __half* A = asel ? d_Ah : d_Xh;
    const __half* Ball = (bsel == 0) ? d_Wgh : (bsel == 1) ? d_Wuh : d_Wdh;
    float* C = (csel == 0) ? d_G : (csel == 1) ? d_U : d_Y;
    const __half* B = Ball + (size_t)e * N * K;

    extern __shared__ char sm[];
    int* s_pid = (int*)(sm + PIDOFF);
    uint32_t smbase = smem_u32(sm);

    int tid = threadIdx.x;
    int lane = tid & 31;
    int wid = tid >> 5;
    int wm = wid & 1;          // 0..1  (64 rows)
    int wn = wid >> 1;         // 0..3  (32 cols)

    if (tid < 128) {
        int lp = mbase + tid;
        s_pid[tid] = d_list[e * CAP + (lp < n_e ? lp : mbase)];
    }
    __syncthreads();

    // loader: 1024 16B-chunks per stage (rows 0-127 A, 128-255 B), 4 chunks/thread
    const char* gP[4];
    uint32_t sS[4];
#pragma unroll
    for (int i = 0; i < 4; i++) {
        int idx = tid + i * 256;          // 0..1023
        int row = idx >> 2;               // 0..255
        int c16 = (idx & 3) * 16;         // byte offset within 64B row
        if (row < 128) {
            gP[i] = (const char*)(A + (size_t)(s_pid[row] >> shift) * lda) + c16;
        } else {
            gP[i] = (const char*)(B + (size_t)(nbase + row - 128) * K) + c16;
        }
        sS[i] = (uint32_t)(row * RS2B + c16);
    }

    int KT = K / BK;

    auto issue = [&](int st, int kb) {
        uint32_t sb = smbase + (uint32_t)(st * TILE_B);
        uint32_t go = (uint32_t)(kb * 64);        // BK halfs = 64 bytes
#pragma unroll
        for (int i = 0; i < 4; i++) cp16(sb + sS[i], gP[i] + go);
        asm volatile("cp.async.commit_group;" ::: "memory");
    };

    issue(0, 0);
    issue(1, 1);

    float acc[4][4][4];
#pragma unroll
    for (int mt = 0; mt < 4; mt++)
#pragma unroll
        for (int nt = 0; nt < 4; nt++)
#pragma unroll
            for (int q = 0; q < 4; q++) acc[mt][nt][q] = 0.f;

    // ldmatrix per-lane addresses within a stage
    int lg = lane >> 3, lr = lane & 7;
    uint32_t aoff[4];
#pragma unroll
    for (int mt = 0; mt < 4; mt++) {
        int row = wm * 64 + mt * 16 + ((lg & 1) << 3) + lr;
        aoff[mt] = (uint32_t)(row * RS2B + ((lg >> 1) << 4));
    }
    uint32_t boff[2];
#pragma unroll
    for (int ntp = 0; ntp < 2; ntp++) {
        int row = 128 + wn * 32 + ntp * 16 + ((lg >> 1) << 3) + lr;
        boff[ntp] = (uint32_t)(row * RS2B + ((lg & 1) << 4));
    }

    for (int kb = 0; kb < KT; kb++) {
        int st = kb % NSTAGE;
        if (kb + 2 < KT) {
            __syncthreads();                       // WAR: stage (kb+2)%3 consumed
            issue((kb + 2) % NSTAGE, kb + 2);
            asm volatile("cp.async.wait_group 2;" ::: "memory");
        } else if (kb + 1 < KT) {
            asm volatile("cp.async.wait_group 1;" ::: "memory");
        } else {
            asm volatile("cp.async.wait_group 0;" ::: "memory");
        }
        __syncthreads();                           // stage kb visible

        uint32_t stb = smbase + (uint32_t)(st * TILE_B);
#pragma unroll
        for (int ks = 0; ks < 2; ks++) {
            uint32_t kbyte = (uint32_t)(ks * 32);  // 16 halfs
            uint32_t af[4][4], bf[2][4];
#pragma unroll
            for (int mt = 0; mt < 4; mt++) ldm4(af[mt], stb + aoff[mt] + kbyte);
#pragma unroll
            for (int ntp = 0; ntp < 2; ntp++) ldm4(bf[ntp], stb + boff[ntp] + kbyte);
#pragma unroll
            for (int mt = 0; mt < 4; mt++)
#pragma unroll
                for (int ntp = 0; ntp < 2; ntp++) {
                    mma_f16(acc[mt][2 * ntp],     af[mt], &bf[ntp][0]);
                    mma_f16(acc[mt][2 * ntp + 1], af[mt], &bf[ntp][2]);
                }
        }
    }

    // epilogue: scatter accum rows via pid list
    int gid = lane >> 2;
    int tig = lane & 3;
#pragma unroll
    for (int mt = 0; mt < 4; mt++) {
        int mrow0 = wm * 64 + mt * 16 + gid;
        int mrow1 = mrow0 + 8;
        bool v0 = (mbase + mrow0) < n_e;
        bool v1 = (mbase + mrow1) < n_e;
        float* c0 = v0 ? (C + (size_t)s_pid[mrow0] * N + nbase + wn * 32 + tig * 2) : (float*)0;
        float* c1 = v1 ? (C + (size_t)s_pid[mrow1] * N + nbase + wn * 32 + tig * 2) : (float*)0;
#pragma unroll
        for (int nt = 0; nt < 4; nt++) {
            if (v0) *(float2*)(c0 + nt * 8) = make_float2(acc[mt][nt][0], acc[mt][nt][1]);
            if (v1) *(float2*)(c1 + nt * 8) = make_float2(acc[mt][nt][2], acc[mt][nt][3]);
        }
    }
}

// ---------------- elementwise ----------------
// act = fp16(silu(G) * U)  (same rounding point as previous in-GEMM staging cvt)
__global__ void act_kernel() {
    size_t i = (size_t)blockIdx.x * blockDim.x + threadIdx.x;
    if (i >= (size_t)NPAIRS * INTER / 4) return;
    float4 g = ((const float4*)d_G)[i];
    float4 u = ((const float4*)d_U)[i];
    float ox = g.x / (1.f + expf(-g.x)) * u.x;
    float oy = g.y / (1.f + expf(-g.y)) * u.y;
    float oz = g.z / (1.f + expf(-g.z)) * u.z;
    float ow = g.w / (1.f + expf(-g.w)) * u.w;
    ((uint2*)d_Ah)[i] = make_uint2(packf16(ox, oy), packf16(oz, ow));
}

__global__ void combine_kernel(float* __restrict__ out) {
    int idx = blockIdx.x * blockDim.x + threadIdx.x;
    if (idx >= T_TOKENS * HIDDEN / 4) return;
    int t = idx / (HIDDEN / 4);
    int h4 = idx % (HIDDEN / 4);
    float w0 = d_wgt[2 * t], w1 = d_wgt[2 * t + 1];
    float4 a = ((const float4*)d_Y)[(size_t)(2 * t) * (HIDDEN / 4) + h4];
    float4 b = ((const float4*)d_Y)[(size_t)(2 * t + 1) * (HIDDEN / 4) + h4];
    float4 o;
    o.x = w0 * a.x + w1 * b.x;
    o.y = w0 * a.y + w1 * b.y;
    o.z = w0 * a.z + w1 * b.z;
    o.w = w0 * a.w + w1 * b.w;
    ((float4*)out)[idx] = o;
}

// ---------------- launch ----------------
extern "C" void kernel_launch(void* const* d_in, const int* in_sizes, int n_in,
                              void* d_out, int out_size) {
    const float* x  = (const float*)d_in[0];
    const float* wr = (const float*)d_in[1];
    const float* wg = (const float*)d_in[2];
    const float* wu = (const float*)d_in[3];
    const float* wd = (const float*)d_in[4];
    float* out = (float*)d_out;

    cudaFuncSetAttribute(gemm_h, cudaFuncAttributeMaxDynamicSharedMemorySize, DYN_BYTES);

    init_kernel<<<1, 32>>>();
    router_kernel<<<T_TOKENS / 8, 256>>>(x, wr);
    compact_kernel<<<NPAIRS / 256, 256>>>();

    // fp32 -> fp16 conversions (weights + x)
    int w4 = WSZ / 4;
    cvt_half_kernel<<<(w4 + 255) / 256, 256>>>(wg, 0, w4);
    cvt_half_kernel<<<(w4 + 255) / 256, 256>>>(wu, 1, w4);
    cvt_half_kernel<<<(w4 + 255) / 256, 256>>>(wd, 2, w4);
    int x4 = T_TOKENS * HIDDEN / 4;
    cvt_half_kernel<<<(x4 + 255) / 256, 256>>>(x, 3, x4);

    // G = x @ Wg^T   (N=INTER, K=HIDDEN)
    dim3 g1(INTER / 128, CAP / 128, NEXP);
    gemm_h<<<g1, 256, DYN_BYTES>>>(INTER, HIDDEN, HIDDEN, 1, 0, 0, 0);
    // U = x @ Wu^T
    gemm_h<<<g1, 256, DYN_BYTES>>>(INTER, HIDDEN, HIDDEN, 1, 0, 1, 1);

    // act = fp16(silu(G) * U)
    size_t total4 = (size_t)NPAIRS * INTER / 4;
    act_kernel<<<(unsigned)((total4 + 255) / 256), 256>>>();

    // Y = act @ Wd^T  (N=HIDDEN, K=INTER)
    dim3 g3(HIDDEN / 128, CAP / 128, NEXP);
    gemm_h<<<g3, 256, DYN_BYTES>>>(HIDDEN, INTER, INTER, 0, 1, 2, 2);

    combine_kernel<<<(T_TOKENS * HIDDEN / 4) / 256, 256>>>(out);
}

// round 16
// speedup vs baseline: 1.2132x; 1.0111x over previous
#include <cuda_runtime.h>
#include <cuda_fp16.h>
#include <math.h>
#include <stdint.h>

// Problem constants
#define T_TOKENS 2048
#define HIDDEN   2048
#define INTER    5632
#define NEXP     8
#define TOPK     2
#define NPAIRS   (T_TOKENS * TOPK)   // 4096
#define CAP      2048
#define WSZ      (NEXP * INTER * HIDDEN)   // elements per weight tensor (92.3M)

// ---------------- device scratch ----------------
__device__ int d_cnt[NEXP];
__device__ int d_list[NEXP * CAP];
__device__ int d_eid[NPAIRS];
__device__ float d_wgt[NPAIRS];

__device__ __align__(16) __half d_Wgh[(size_t)WSZ];
__device__ __align__(16) __half d_Wuh[(size_t)WSZ];
__device__ __align__(16) __half d_Wdh[(size_t)WSZ];
__device__ __align__(16) __half d_Xh[(size_t)T_TOKENS * HIDDEN];
__device__ __align__(16) __half d_Ah[(size_t)NPAIRS * INTER];   // fp16 act
__device__ __align__(16) float d_G[(size_t)NPAIRS * INTER];     // gate (fp32)
__device__ __align__(16) float d_U[(size_t)NPAIRS * INTER];     // up (fp32)
__device__ __align__(16) float d_Y[(size_t)NPAIRS * HIDDEN];    // down output (fp32)

// ---------------- small kernels ----------------
__global__ void init_kernel() {
    if (threadIdx.x < NEXP) d_cnt[threadIdx.x] = 0;
}

__global__ void router_kernel(const float* __restrict__ x, const float* __restrict__ wr) {
    int warp = threadIdx.x >> 5;
    int lane = threadIdx.x & 31;
    int t = blockIdx.x * 8 + warp;
    if (t >= T_TOKENS) return;

    float acc[NEXP];
#pragma unroll
    for (int e = 0; e < NEXP; e++) acc[e] = 0.f;
    const float* xr = x + (size_t)t * HIDDEN;
    for (int j = lane; j < HIDDEN; j += 32) {
        float xv = xr[j];
#pragma unroll
        for (int e = 0; e < NEXP; e++) acc[e] += xv * wr[e * HIDDEN + j];
    }
#pragma unroll
    for (int e = 0; e < NEXP; e++) {
#pragma unroll
        for (int off = 16; off; off >>= 1)
            acc[e] += __shfl_xor_sync(0xffffffffu, acc[e], off);
    }
    if (lane == 0) {
        int e0 = 0;
#pragma unroll
        for (int e = 1; e < NEXP; e++) if (acc[e] > acc[e0]) e0 = e;
        int e1 = -1;
#pragma unroll
        for (int e = 0; e < NEXP; e++) {
            if (e == e0) continue;
            if (e1 < 0 || acc[e] > acc[e1]) e1 = e;
        }
        float v0 = acc[e0], v1 = acc[e1];
        float w1 = 1.f / (1.f + expf(v0 - v1));
        float w0 = 1.f - w1;
        d_eid[2 * t] = e0;  d_eid[2 * t + 1] = e1;
        d_wgt[2 * t] = w0;  d_wgt[2 * t + 1] = w1;
    }
}

__global__ void compact_kernel() {
    int p = blockIdx.x * blockDim.x + threadIdx.x;
    if (p >= NPAIRS) return;
    int e = d_eid[p];
    int pos = atomicAdd(&d_cnt[e], 1);
    d_list[e * CAP + pos] = p;
}

// ---------------- helpers ----------------
__device__ __forceinline__ uint32_t smem_u32(const void* p) {
    uint32_t a;
    asm("{ .reg .u64 t; cvta.to.shared.u64 t, %1; cvt.u32.u64 %0, t; }" : "=r"(a) : "l"(p));
    return a;
}
__device__ __forceinline__ uint32_t packf16(float a, float b) {   // lo=a, hi=b
    uint32_t d;
    asm("cvt.rn.f16x2.f32 %0, %1, %2;" : "=r"(d) : "f"(b), "f"(a));
    return d;
}
__device__ __forceinline__ void mma_f16(float* c, const uint32_t* a, const uint32_t* b) {
    asm volatile("mma.sync.aligned.m16n8k16.row.col.f32.f16.f16.f32 "
                 "{%0,%1,%2,%3}, {%4,%5,%6,%7}, {%8,%9}, {%0,%1,%2,%3};"
                 : "+f"(c[0]), "+f"(c[1]), "+f"(c[2]), "+f"(c[3])
                 : "r"(a[0]), "r"(a[1]), "r"(a[2]), "r"(a[3]),
                   "r"(b[0]), "r"(b[1]));
}
__device__ __forceinline__ void ldm4(uint32_t* d, uint32_t addr) {
    asm volatile("ldmatrix.sync.aligned.m8n8.x4.shared.b16 {%0,%1,%2,%3}, [%4];"
                 : "=r"(d[0]), "=r"(d[1]), "=r"(d[2]), "=r"(d[3]) : "r"(addr));
}
__device__ __forceinline__ void cp16(uint32_t smem_dst, const void* gptr) {
    asm volatile("cp.async.cg.shared.global [%0], [%1], 16;" :: "r"(smem_dst), "l"(gptr));
}

// ---------------- fp32 -> fp16 streaming conversion ----------------
// All three weight matrices in one launch (y = which matrix); x separately.
__global__ __launch_bounds__(256) void cvt_w_kernel(const float* __restrict__ wg,
                                                    const float* __restrict__ wu,
                                                    const float* __restrict__ wd, int n4) {
    int i = blockIdx.x * blockDim.x + threadIdx.x;
    if (i >= n4) return;
    const float* src = (blockIdx.y == 0) ? wg : (blockIdx.y == 1) ? wu : wd;
    __half* dst = (blockIdx.y == 0) ? d_Wgh : (blockIdx.y == 1) ? d_Wuh : d_Wdh;
    float4 v = ((const float4*)src)[i];
    ((uint2*)dst)[i] = make_uint2(packf16(v.x, v.y), packf16(v.z, v.w));
}
__global__ __launch_bounds__(256) void cvt_x_kernel(const float* __restrict__ x, int n4) {
    int i = blockIdx.x * blockDim.x + threadIdx.x;
    if (i >= n4) return;
    float4 v = ((const float4*)x)[i];
    ((uint2*)d_Xh)[i] = make_uint2(packf16(v.x, v.y), packf16(v.z, v.w));
}

// ---------------- expert-grouped pure-fp16 tensor GEMM ----------------
// C[pid][n] = sum_k A[pid>>shift][k] * B_e[n][k]   (A, B fp16; C fp32)
// Tile: BM=128, BN=256, BK=32. 256 threads, 8 warps in 2(m) x 4(n), warp tile 64x64.
#define BK 32
#define RS2B 80                                 // fp16 row stride bytes (64B data + 16 pad)
#define TILE_B (384 * RS2B)                     // stage: A rows 0-127, B rows 128-383
#define NSTAGE 3
#define PIDOFF (NSTAGE * TILE_B)
#define DYN_BYTES (PIDOFF + 128 * 4 + 16)

__global__ __launch_bounds__(256, 1)
void gemm_h(int N, int K, int lda, int shift, int asel, int bsel, int csel)
{
    int e = blockIdx.z;
    int n_e = d_cnt[e];
    int mbase = blockIdx.y * 128;
    if (mbase >= n_e) return;
    int nbase = blockIdx.x * 256;

    const __half* A = asel ? d_Ah : d_Xh;
    const __half* Ball = (bsel == 0) ? d_Wgh : (bsel == 1) ? d_Wuh : d_Wdh;
    float* C = (csel == 0) ? d_G : (csel == 1) ? d_U : d_Y;
    const __half* B = Ball + (size_t)e * N * K;

    extern __shared__ char sm[];
    int* s_pid = (int*)(sm + PIDOFF);
    uint32_t smbase = smem_u32(sm);

    int tid = threadIdx.x;
    int lane = tid & 31;
    int wid = tid >> 5;
    int wm = wid & 1;          // 0..1  (64 rows)
    int wn = wid >> 1;         // 0..3  (64 cols)

    if (tid < 128) {
        int lp = mbase + tid;
        s_pid[tid] = d_list[e * CAP + (lp < n_e ? lp : mbase)];
    }
    __syncthreads();

    // loader: 1536 16B-chunks per stage (rows 0-127 A, 128-383 B), 6 chunks/thread
    const char* gP[6];
    uint32_t sS[6];
#pragma unroll
    for (int i = 0; i < 6; i++) {
        int idx = tid + i * 256;          // 0..1535
        int row = idx >> 2;               // 0..383
        int c16 = (idx & 3) * 16;         // byte offset within 64B row
        if (row < 128) {
            gP[i] = (const char*)(A + (size_t)(s_pid[row] >> shift) * lda) + c16;
        } else {
            gP[i] = (const char*)(B + (size_t)(nbase + row - 128) * K) + c16;
        }
        sS[i] = (uint32_t)(row * RS2B + c16);
    }

    int KT = K / BK;

    auto issue = [&](int st, int kb) {
        uint32_t sb = smbase + (uint32_t)(st * TILE_B);
        uint32_t go = (uint32_t)(kb * 64);        // BK halfs = 64 bytes
#pragma unroll
        for (int i = 0; i < 6; i++) cp16(sb + sS[i], gP[i] + go);
        asm volatile("cp.async.commit_group;" ::: "memory");
    };

    issue(0, 0);
    issue(1, 1);

    float acc[4][8][4];
#pragma unroll
    for (int mt = 0; mt < 4; mt++)
#pragma unroll
        for (int nt = 0; nt < 8; nt++)
#pragma unroll
            for (int q = 0; q < 4; q++) acc[mt][nt][q] = 0.f;

    // ldmatrix per-lane addresses within a stage
    int lg = lane >> 3, lr = lane & 7;
    uint32_t aoff[4];
#pragma unroll
    for (int mt = 0; mt < 4; mt++) {
        int row = wm * 64 + mt * 16 + ((lg & 1) << 3) + lr;
        aoff[mt] = (uint32_t)(row * RS2B + ((lg >> 1) << 4));
    }
    uint32_t boff[4];
#pragma unroll
    for (int ntp = 0; ntp < 4; ntp++) {
        int row = 128 + wn * 64 + ntp * 16 + ((lg >> 1) << 3) + lr;
        boff[ntp] = (uint32_t)(row * RS2B + ((lg & 1) << 4));
    }

    for (int kb = 0; kb < KT; kb++) {
        int st = kb % NSTAGE;
        if (kb + 2 < KT) {
            __syncthreads();                       // WAR: stage (kb+2)%3 consumed
            issue((kb + 2) % NSTAGE, kb + 2);
            asm volatile("cp.async.wait_group 2;" ::: "memory");
        } else if (kb + 1 < KT) {
            asm volatile("cp.async.wait_group 1;" ::: "memory");
        } else {
            asm volatile("cp.async.wait_group 0;" ::: "memory");
        }
        __syncthreads();                           // stage kb visible

        uint32_t stb = smbase + (uint32_t)(st * TILE_B);
#pragma unroll
        for (int ks = 0; ks < 2; ks++) {
            uint32_t kbyte = (uint32_t)(ks * 32);  // 16 halfs
            uint32_t af[4][4], bf[4][4];
#pragma unroll
            for (int mt = 0; mt < 4; mt++) ldm4(af[mt], stb + aoff[mt] + kbyte);
#pragma unroll
            for (int ntp = 0; ntp < 4; ntp++) ldm4(bf[ntp], stb + boff[ntp] + kbyte);
#pragma unroll
            for (int mt = 0; mt < 4; mt++)
#pragma unroll
                for (int ntp = 0; ntp < 4; ntp++) {
                    mma_f16(acc[mt][2 * ntp],     af[mt], &bf[ntp][0]);
                    mma_f16(acc[mt][2 * ntp + 1], af[mt], &bf[ntp][2]);
                }
        }
    }

    // epilogue: scatter accum rows via pid list
    int gid = lane >> 2;
    int tig = lane & 3;
#pragma unroll
    for (int mt = 0; mt < 4; mt++) {
        int mrow0 = wm * 64 + mt * 16 + gid;
        int mrow1 = mrow0 + 8;
        bool v0 = (mbase + mrow0) < n_e;
        bool v1 = (mbase + mrow1) < n_e;
        float* c0 = v0 ? (C + (size_t)s_pid[mrow0] * N + nbase + wn * 64 + tig * 2) : (float*)0;
        float* c1 = v1 ? (C + (size_t)s_pid[mrow1] * N + nbase + wn * 64 + tig * 2) : (float*)0;
#pragma unroll
        for (int nt = 0; nt < 8; nt++) {
            if (v0) *(float2*)(c0 + nt * 8) = make_float2(acc[mt][nt][0], acc[mt][nt][1]);
            if (v1) *(float2*)(c1 + nt * 8) = make_float2(acc[mt][nt][2], acc[mt][nt][3]);
        }
    }
}

// ---------------- elementwise ----------------
// act = fp16(silu(G) * U)
__global__ void act_kernel() {
    size_t i = (size_t)blockIdx.x * blockDim.x + threadIdx.x;
    if (i >= (size_t)NPAIRS * INTER / 4) return;
    float4 g = ((const float4*)d_G)[i];
    float4 u = ((const float4*)d_U)[i];
    float ox = g.x / (1.f + expf(-g.x)) * u.x;
    float oy = g.y / (1.f + expf(-g.y)) * u.y;
    float oz = g.z / (1.f + expf(-g.z)) * u.z;
    float ow = g.w / (1.f + expf(-g.w)) * u.w;
    ((uint2*)d_Ah)[i] = make_uint2(packf16(ox, oy), packf16(oz, ow));
}

__global__ void combine_kernel(float* __restrict__ out) {
    int idx = blockIdx.x * blockDim.x + threadIdx.x;
    if (idx >= T_TOKENS * HIDDEN / 4) return;
    int t = idx / (HIDDEN / 4);
    int h4 = idx % (HIDDEN / 4);
    float w0 = d_wgt[2 * t], w1 = d_wgt[2 * t + 1];
    float4 a = ((const float4*)d_Y)[(size_t)(2 * t) * (HIDDEN / 4) + h4];
    float4 b = ((const float4*)d_Y)[(size_t)(2 * t + 1) * (HIDDEN / 4) + h4];
    float4 o;
    o.x = w0 * a.x + w1 * b.x;
    o.y = w0 * a.y + w1 * b.y;
    o.z = w0 * a.z + w1 * b.z;
    o.w = w0 * a.w + w1 * b.w;
    ((float4*)out)[idx] = o;
}

// ---------------- launch ----------------
extern "C" void kernel_launch(void* const* d_in, const int* in_sizes, int n_in,
                              void* d_out, int out_size) {
    const float* x  = (const float*)d_in[0];
    const float* wr = (const float*)d_in[1];
    const float* wg = (const float*)d_in[2];
    const float* wu = (const float*)d_in[3];
    const float* wd = (const float*)d_in[4];
    float* out = (float*)d_out;

    cudaFuncSetAttribute(gemm_h, cudaFuncAttributeMaxDynamicSharedMemorySize, DYN_BYTES);

    init_kernel<<<1, 32>>>();
    router_kernel<<<T_TOKENS / 8, 256>>>(x, wr);
    compact_kernel<<<NPAIRS / 256, 256>>>();

    // fp32 -> fp16 conversions (weights in one launch + x)
    int w4 = WSZ / 4;
    dim3 cg((w4 + 255) / 256, 3, 1);
    cvt_w_kernel<<<cg, 256>>>(wg, wu, wd, w4);
    int x4 = T_TOKENS * HIDDEN / 4;
    cvt_x_kernel<<<(x4 + 255) / 256, 256>>>(x, x4);

    // G = x @ Wg^T   (N=INTER, K=HIDDEN)
    dim3 g1(INTER / 256, CAP / 128, NEXP);
    gemm_h<<<g1, 256, DYN_BYTES>>>(INTER, HIDDEN, HIDDEN, 1, 0, 0, 0);
    // U = x @ Wu^T
    gemm_h<<<g1, 256, DYN_BYTES>>>(INTER, HIDDEN, HIDDEN, 1, 0, 1, 1);

    // act = fp16(silu(G) * U)
    size_t total4 = (size_t)NPAIRS * INTER / 4;
    act_kernel<<<(unsigned)((total4 + 255) / 256), 256>>>();

    // Y = act @ Wd^T  (N=HIDDEN, K=INTER)
    dim3 g3(HIDDEN / 256, CAP / 128, NEXP);
    gemm_h<<<g3, 256, DYN_BYTES>>>(HIDDEN, INTER, INTER, 0, 1, 2, 2);

    combine_kernel<<<(T_TOKENS * HIDDEN / 4) / 256, 256>>>(out);
}

// round 17
// speedup vs baseline: 1.2179x; 1.0039x over previous
#include <cuda_runtime.h>
#include <cuda_fp16.h>
#include <math.h>
#include <stdint.h>

// Problem constants
#define T_TOKENS 2048
#define HIDDEN   2048
#define INTER    5632
#define NEXP     8
#define TOPK     2
#define NPAIRS   (T_TOKENS * TOPK)   // 4096
#define CAP      2048
#define WSZ      (NEXP * INTER * HIDDEN)   // elements per weight tensor (92.3M)

// ---------------- device scratch ----------------
__device__ int d_cnt[NEXP];
__device__ int d_list[NEXP * CAP];
__device__ int d_eid[NPAIRS];
__device__ float d_wgt[NPAIRS];

__device__ __align__(16) __half d_Wgh[(size_t)WSZ];
__device__ __align__(16) __half d_Wuh[(size_t)WSZ];
__device__ __align__(16) __half d_Wdh[(size_t)WSZ];
__device__ __align__(16) __half d_Xh[(size_t)T_TOKENS * HIDDEN];
__device__ __align__(16) __half d_Ah[(size_t)NPAIRS * INTER];   // fp16 act
__device__ __align__(16) float d_G[(size_t)NPAIRS * INTER];     // gate (fp32)
__device__ __align__(16) float d_U[(size_t)NPAIRS * INTER];     // up (fp32)
__device__ __align__(16) float d_Y[(size_t)NPAIRS * HIDDEN];    // down output (fp32)

// ---------------- small kernels ----------------
__global__ void init_kernel() {
    if (threadIdx.x < NEXP) d_cnt[threadIdx.x] = 0;
}

__global__ void router_kernel(const float* __restrict__ x, const float* __restrict__ wr) {
    int warp = threadIdx.x >> 5;
    int lane = threadIdx.x & 31;
    int t = blockIdx.x * 8 + warp;
    if (t >= T_TOKENS) return;

    float acc[NEXP];
#pragma unroll
    for (int e = 0; e < NEXP; e++) acc[e] = 0.f;
    const float* xr = x + (size_t)t * HIDDEN;
    for (int j = lane; j < HIDDEN; j += 32) {
        float xv = xr[j];
#pragma unroll
        for (int e = 0; e < NEXP; e++) acc[e] += xv * wr[e * HIDDEN + j];
    }
#pragma unroll
    for (int e = 0; e < NEXP; e++) {
#pragma unroll
        for (int off = 16; off; off >>= 1)
            acc[e] += __shfl_xor_sync(0xffffffffu, acc[e], off);
    }
    if (lane == 0) {
        int e0 = 0;
#pragma unroll
        for (int e = 1; e < NEXP; e++) if (acc[e] > acc[e0]) e0 = e;
        int e1 = -1;
#pragma unroll
        for (int e = 0; e < NEXP; e++) {
            if (e == e0) continue;
            if (e1 < 0 || acc[e] > acc[e1]) e1 = e;
        }
        float v0 = acc[e0], v1 = acc[e1];
        float w1 = 1.f / (1.f + expf(v0 - v1));
        float w0 = 1.f - w1;
        d_eid[2 * t] = e0;  d_eid[2 * t + 1] = e1;
        d_wgt[2 * t] = w0;  d_wgt[2 * t + 1] = w1;
    }
}

__global__ void compact_kernel() {
    int p = blockIdx.x * blockDim.x + threadIdx.x;
    if (p >= NPAIRS) return;
    int e = d_eid[p];
    int pos = atomicAdd(&d_cnt[e], 1);
    d_list[e * CAP + pos] = p;
}

// ---------------- helpers ----------------
__device__ __forceinline__ uint32_t smem_u32(const void* p) {
    uint32_t a;
    asm("{ .reg .u64 t; cvta.to.shared.u64 t, %1; cvt.u32.u64 %0, t; }" : "=r"(a) : "l"(p));
    return a;
}
__device__ __forceinline__ uint32_t packf16(float a, float b) {   // lo=a, hi=b
    uint32_t d;
    asm("cvt.rn.f16x2.f32 %0, %1, %2;" : "=r"(d) : "f"(b), "f"(a));
    return d;
}
__device__ __forceinline__ void mma_f16(float* c, const uint32_t* a, const uint32_t* b) {
    asm volatile("mma.sync.aligned.m16n8k16.row.col.f32.f16.f16.f32 "
                 "{%0,%1,%2,%3}, {%4,%5,%6,%7}, {%8,%9}, {%0,%1,%2,%3};"
                 : "+f"(c[0]), "+f"(c[1]), "+f"(c[2]), "+f"(c[3])
                 : "r"(a[0]), "r"(a[1]), "r"(a[2]), "r"(a[3]),
                   "r"(b[0]), "r"(b[1]));
}
__device__ __forceinline__ void ldm4(uint32_t* d, uint32_t addr) {
    asm volatile("ldmatrix.sync.aligned.m8n8.x4.shared.b16 {%0,%1,%2,%3}, [%4];"
                 : "=r"(d[0]), "=r"(d[1]), "=r"(d[2]), "=r"(d[3]) : "r"(addr));
}
__device__ __forceinline__ void cp16(uint32_t smem_dst, const void* gptr) {
    asm volatile("cp.async.cg.shared.global [%0], [%1], 16;" :: "r"(smem_dst), "l"(gptr));
}

// ---------------- fp32 -> fp16 streaming conversion ----------------
__global__ __launch_bounds__(256) void cvt_w_kernel(const float* __restrict__ wg,
                                                    const float* __restrict__ wu,
                                                    const float* __restrict__ wd, int n4) {
    int i = blockIdx.x * blockDim.x + threadIdx.x;
    if (i >= n4) return;
    const float* src = (blockIdx.y == 0) ? wg : (blockIdx.y == 1) ? wu : wd;
    __half* dst = (blockIdx.y == 0) ? d_Wgh : (blockIdx.y == 1) ? d_Wuh : d_Wdh;
    float4 v = ((const float4*)src)[i];
    ((uint2*)dst)[i] = make_uint2(packf16(v.x, v.y), packf16(v.z, v.w));
}
__global__ __launch_bounds__(256) void cvt_x_kernel(const float* __restrict__ x, int n4) {
    int i = blockIdx.x * blockDim.x + threadIdx.x;
    if (i >= n4) return;
    float4 v = ((const float4*)x)[i];
    ((uint2*)d_Xh)[i] = make_uint2(packf16(v.x, v.y), packf16(v.z, v.w));
}

// ---------------- expert-grouped pure-fp16 tensor GEMM (4-stage, 1 sync/kb) ----------------
// C[pid][n] = sum_k A[pid>>shift][k] * B_e[n][k]   (A, B fp16; C fp32)
// Tile: BM=128, BN=256, BK=32. 256 threads, 8 warps in 2(m) x 4(n), warp tile 64x64.
#define BK 32
#define RS2B 80                                 // fp16 row stride bytes (64B data + 16 pad)
#define TILE_B (384 * RS2B)                     // stage: A rows 0-127, B rows 128-383
#define NSTAGE 4
#define PIDOFF (NSTAGE * TILE_B)
#define DYN_BYTES (PIDOFF + 128 * 4 + 16)

__global__ __launch_bounds__(256, 1)
void gemm_h(int N, int K, int lda, int shift, int asel, int bsel, int csel)
{
    int e = blockIdx.z;
    int n_e = d_cnt[e];
    int mbase = blockIdx.y * 128;
    if (mbase >= n_e) return;
    int nbase = blockIdx.x * 256;

    const __half* A = asel ? d_Ah : d_Xh;
    const __half* Ball = (bsel == 0) ? d_Wgh : (bsel == 1) ? d_Wuh : d_Wdh;
    float* C = (csel == 0) ? d_G : (csel == 1) ? d_U : d_Y;
    const __half* B = Ball + (size_t)e * N * K;

    extern __shared__ char sm[];
    int* s_pid = (int*)(sm + PIDOFF);
    uint32_t smbase = smem_u32(sm);

    int tid = threadIdx.x;
    int lane = tid & 31;
    int wid = tid >> 5;
    int wm = wid & 1;          // 0..1  (64 rows)
    int wn = wid >> 1;         // 0..3  (64 cols)

    if (tid < 128) {
        int lp = mbase + tid;
        s_pid[tid] = d_list[e * CAP + (lp < n_e ? lp : mbase)];
    }
    __syncthreads();

    // loader: 1536 16B-chunks per stage (rows 0-127 A, 128-383 B), 6 chunks/thread
    const char* gP[6];
    uint32_t sS[6];
#pragma unroll
    for (int i = 0; i < 6; i++) {
        int idx = tid + i * 256;          // 0..1535
        int row = idx >> 2;               // 0..383
        int c16 = (idx & 3) * 16;
        if (row < 128) {
            gP[i] = (const char*)(A + (size_t)(s_pid[row] >> shift) * lda) + c16;
        } else {
            gP[i] = (const char*)(B + (size_t)(nbase + row - 128) * K) + c16;
        }
        sS[i] = (uint32_t)(row * RS2B + c16);
    }

    int KT = K / BK;

    auto issue = [&](int st, int kb) {
        uint32_t sb = smbase + (uint32_t)(st * TILE_B);
        uint32_t go = (uint32_t)(kb * 64);        // BK halfs = 64 bytes
#pragma unroll
        for (int i = 0; i < 6; i++) cp16(sb + sS[i], gP[i] + go);
        asm volatile("cp.async.commit_group;" ::: "memory");
    };

    // prologue: stages 0..2
    issue(0, 0);
    issue(1, 1);
    issue(2, 2);

    float acc[4][8][4];
#pragma unroll
    for (int mt = 0; mt < 4; mt++)
#pragma unroll
        for (int nt = 0; nt < 8; nt++)
#pragma unroll
            for (int q = 0; q < 4; q++) acc[mt][nt][q] = 0.f;

    // ldmatrix per-lane addresses within a stage
    int lg = lane >> 3, lr = lane & 7;
    uint32_t aoff[4];
#pragma unroll
    for (int mt = 0; mt < 4; mt++) {
        int row = wm * 64 + mt * 16 + ((lg & 1) << 3) + lr;
        aoff[mt] = (uint32_t)(row * RS2B + ((lg >> 1) << 4));
    }
    uint32_t boff[4];
#pragma unroll
    for (int ntp = 0; ntp < 4; ntp++) {
        int row = 128 + wn * 64 + ntp * 16 + ((lg >> 1) << 3) + lr;
        boff[ntp] = (uint32_t)(row * RS2B + ((lg & 1) << 4));
    }

    for (int kb = 0; kb < KT; kb++) {
        int st = kb % NSTAGE;
        // wait: group kb complete (groups complete in order)
        if (kb + 3 <= KT) {
            asm volatile("cp.async.wait_group 2;" ::: "memory");
        } else if (kb + 2 <= KT) {
            asm volatile("cp.async.wait_group 1;" ::: "memory");
        } else {
            asm volatile("cp.async.wait_group 0;" ::: "memory");
        }
        __syncthreads();   // stage kb visible everywhere; stage (kb-1)%4 reads all done

        if (kb + 3 < KT) issue((kb + 3) % NSTAGE, kb + 3);

        uint32_t stb = smbase + (uint32_t)(st * TILE_B);
#pragma unroll
        for (int ks = 0; ks < 2; ks++) {
            uint32_t kbyte = (uint32_t)(ks * 32);  // 16 halfs
            uint32_t af[4][4], bf[4][4];
#pragma unroll
            for (int mt = 0; mt < 4; mt++) ldm4(af[mt], stb + aoff[mt] + kbyte);
#pragma unroll
            for (int ntp = 0; ntp < 4; ntp++) ldm4(bf[ntp], stb + boff[ntp] + kbyte);
#pragma unroll
            for (int mt = 0; mt < 4; mt++)
#pragma unroll
                for (int ntp = 0; ntp < 4; ntp++) {
                    mma_f16(acc[mt][2 * ntp],     af[mt], &bf[ntp][0]);
                    mma_f16(acc[mt][2 * ntp + 1], af[mt], &bf[ntp][2]);
                }
        }
    }

    // epilogue: scatter accum rows via pid list
    int gid = lane >> 2;
    int tig = lane & 3;
#pragma unroll
    for (int mt = 0; mt < 4; mt++) {
        int mrow0 = wm * 64 + mt * 16 + gid;
        int mrow1 = mrow0 + 8;
        bool v0 = (mbase + mrow0) < n_e;
        bool v1 = (mbase + mrow1) < n_e;
        float* c0 = v0 ? (C + (size_t)s_pid[mrow0] * N + nbase + wn * 64 + tig * 2) : (float*)0;
        float* c1 = v1 ? (C + (size_t)s_pid[mrow1] * N + nbase + wn * 64 + tig * 2) : (float*)0;
#pragma unroll
        for (int nt = 0; nt < 8; nt++) {
            if (v0) *(float2*)(c0 + nt * 8) = make_float2(acc[mt][nt][0], acc[mt][nt][1]);
            if (v1) *(float2*)(c1 + nt * 8) = make_float2(acc[mt][nt][2], acc[mt][nt][3]);
        }
    }
}

// ---------------- elementwise ----------------
// act = fp16(silu(G) * U)
__global__ void act_kernel() {
    size_t i = (size_t)blockIdx.x * blockDim.x + threadIdx.x;
    if (i >= (size_t)NPAIRS * INTER / 4) return;
    float4 g = ((const float4*)d_G)[i];
    float4 u = ((const float4*)d_U)[i];
    float ox = g.x / (1.f + expf(-g.x)) * u.x;
    float oy = g.y / (1.f + expf(-g.y)) * u.y;
    float oz = g.z / (1.f + expf(-g.z)) * u.z;
    float ow = g.w / (1.f + expf(-g.w)) * u.w;
    ((uint2*)d_Ah)[i] = make_uint2(packf16(ox, oy), packf16(oz, ow));
}

__global__ void combine_kernel(float* __restrict__ out) {
    int idx = blockIdx.x * blockDim.x + threadIdx.x;
    if (idx >= T_TOKENS * HIDDEN / 4) return;
    int t = idx / (HIDDEN / 4);
    int h4 = idx % (HIDDEN / 4);
    float w0 = d_wgt[2 * t], w1 = d_wgt[2 * t + 1];
    float4 a = ((const float4*)d_Y)[(size_t)(2 * t) * (HIDDEN / 4) + h4];
    float4 b = ((const float4*)d_Y)[(size_t)(2 * t + 1) * (HIDDEN / 4) + h4];
    float4 o;
    o.x = w0 * a.x + w1 * b.x;
    o.y = w0 * a.y + w1 * b.y;
    o.z = w0 * a.z + w1 * b.z;
    o.w = w0 * a.w + w1 * b.w;
    ((float4*)out)[idx] = o;
}

// ---------------- launch ----------------
extern "C" void kernel_launch(void* const* d_in, const int* in_sizes, int n_in,
                              void* d_out, int out_size) {
    const float* x  = (const float*)d_in[0];
    const float* wr = (const float*)d_in[1];
    const float* wg = (const float*)d_in[2];
    const float* wu = (const float*)d_in[3];
    const float* wd = (const float*)d_in[4];
    float* out = (float*)d_out;

    cudaFuncSetAttribute(gemm_h, cudaFuncAttributeMaxDynamicSharedMemorySize, DYN_BYTES);

    init_kernel<<<1, 32>>>();
    router_kernel<<<T_TOKENS / 8, 256>>>(x, wr);
    compact_kernel<<<NPAIRS / 256, 256>>>();

    int w4 = WSZ / 4;
    dim3 cg((w4 + 255) / 256, 3, 1);
    cvt_w_kernel<<<cg, 256>>>(wg, wu, wd, w4);
    int x4 = T_TOKENS * HIDDEN / 4;
    cvt_x_kernel<<<(x4 + 255) / 256, 256>>>(x, x4);

    // G = x @ Wg^T   (N=INTER, K=HIDDEN)
    dim3 g1(INTER / 256, CAP / 128, NEXP);
    gemm_h<<<g1, 256, DYN_BYTES>>>(INTER, HIDDEN, HIDDEN, 1, 0, 0, 0);
    // U = x @ Wu^T
    gemm_h<<<g1, 256, DYN_BYTES>>>(INTER, HIDDEN, HIDDEN, 1, 0, 1, 1);

    // act = fp16(silu(G) * U)
    size_t total4 = (size_t)NPAIRS * INTER / 4;
    act_kernel<<<(unsigned)((total4 + 255) / 256), 256>>>();

    // Y = act @ Wd^T  (N=HIDDEN, K=INTER)
    dim3 g3(HIDDEN / 256, CAP / 128, NEXP);
    gemm_h<<<g3, 256, DYN_BYTES>>>(HIDDEN, INTER, INTER, 0, 1, 2, 2);

    combine_kernel<<<(T_TOKENS * HIDDEN / 4) / 256, 256>>>(out);
}